// round 12
// baseline (speedup 1.0000x reference)
#include <cuda_runtime.h>
#include <cuda_fp16.h>
#include <math.h>

// Geometry (fixed: importanceMap [32, 1024, 1024] fp32)
#define NBATCH             32
#define ELEM_PER_BATCH     (1 << 20)
#define V4_PER_BATCH       (1 << 18)                 // float4 per batch
#define TOTAL_V4           (NBATCH * V4_PER_BATCH)   // 2^23

// pass 1: 4096 blocks x 128 threads, 16 float4/thread (R9-proven geometry)
#define S_BLOCKS           4096
#define S_THREADS          128
#define S_CHUNKS_PER_BATCH 128
#define S_V4_PER_CHUNK     (V4_PER_BATCH / S_CHUNKS_PER_BATCH) // 2048
#define S_ITERS            (S_V4_PER_CHUNK / S_THREADS)         // 16

// pass 2: 2048 blocks x 256 threads; 1 uint4 of T (8 halfs) -> 2 float4 of O
#define O_BLOCKS           2048
#define O_THREADS          256
#define TOTAL_TU4          (TOTAL_V4 / 2)            // uint4 count = 2^22
#define O_U4_PER_BLOCK     (TOTAL_TU4 / O_BLOCKS)    // 2048
#define O_ITERS            (O_U4_PER_BLOCK / O_THREADS) // 8

// Scratch (static __device__ arrays; no runtime allocation).
// g_t: fp16 t = tanh(x/2), one uint2 (4 halfs) per float4 of X. 64 MB.
__device__ __align__(128) uint2 g_t[TOTAL_V4];
__device__ float2 g_partial[NBATCH][S_CHUNKS_PER_BATCH]; // {sum t, sum t^2}
__device__ float  g_k[NBATCH];                           // k = exp(-c)

__device__ __forceinline__ float tanh_fast(float x) {
    float r; asm("tanh.approx.f32 %0, %1;" : "=f"(r) : "f"(x)); return r;
}
__device__ __forceinline__ float rcp_fast(float x) {
    float r; asm("rcp.approx.f32 %0, %1;" : "=f"(r) : "f"(x)); return r;
}

// ---------------------------------------------------------------------------
// Pass 1: read X (evict-first: don't displace T), compute t = tanh(x/2),
// store fp16 t (64 MB; fits L2 with 2x headroom), accumulate sum t / sum t^2.
// ---------------------------------------------------------------------------
__global__ void __launch_bounds__(S_THREADS)
stats_kernel(const float4* __restrict__ X)
{
    const int batch = blockIdx.x >> 7;
    const int chunk = blockIdx.x & (S_CHUNKS_PER_BATCH - 1);
    const size_t gbase = (size_t)batch * V4_PER_BATCH + (size_t)chunk * S_V4_PER_CHUNK;

    float at = 0.f, at2 = 0.f;
    #pragma unroll
    for (int k = 0; k < S_ITERS; k++) {
        const size_t gi = gbase + (size_t)(k * S_THREADS + threadIdx.x);
        float4 v = __ldcs(&X[gi]);                   // last use of X in pass 1
        float t0 = tanh_fast(0.5f * v.x);
        float t1 = tanh_fast(0.5f * v.y);
        float t2 = tanh_fast(0.5f * v.z);
        float t3 = tanh_fast(0.5f * v.w);
        at += t0;  at2 = __fmaf_rn(t0, t0, at2);
        at += t1;  at2 = __fmaf_rn(t1, t1, at2);
        at += t2;  at2 = __fmaf_rn(t2, t2, at2);
        at += t3;  at2 = __fmaf_rn(t3, t3, at2);

        __half2 h01 = __float22half2_rn(make_float2(t0, t1));
        __half2 h23 = __float22half2_rn(make_float2(t2, t3));
        uint2 pack;
        pack.x = reinterpret_cast<const unsigned&>(h01);
        pack.y = reinterpret_cast<const unsigned&>(h23);
        g_t[gi] = pack;                              // plain store: L2-resident
    }

    // fixed-order reduction -> deterministic
    #pragma unroll
    for (int off = 16; off; off >>= 1) {
        at  += __shfl_xor_sync(0xFFFFFFFFu, at,  off);
        at2 += __shfl_xor_sync(0xFFFFFFFFu, at2, off);
    }
    __shared__ float sh[S_THREADS / 32][2];
    const int warp = threadIdx.x >> 5, lane = threadIdx.x & 31;
    if (lane == 0) { sh[warp][0] = at; sh[warp][1] = at2; }
    __syncthreads();
    if (threadIdx.x == 0) {
        float t0 = 0.f, t1 = 0.f;
        #pragma unroll
        for (int w = 0; w < S_THREADS / 32; w++) { t0 += sh[w][0]; t1 += sh[w][1]; }
        g_partial[batch][chunk] = make_float2(t0, t1);
    }
}

// ---------------------------------------------------------------------------
// Solve: warp w <-> batch w. Linear model in the t-sums:
//   c = -2*sum_t / (N - sum_t2)   (quadratic term ~1e-8 in c; dropped)
// Publish k = exp(-c) (double precision) and emit c.
// ---------------------------------------------------------------------------
__global__ void solve_kernel(float* __restrict__ c_out)
{
    const int batch = threadIdx.x >> 5;
    const int lane  = threadIdx.x & 31;

    float2 p0 = g_partial[batch][lane];
    float2 p1 = g_partial[batch][lane + 32];
    float2 p2 = g_partial[batch][lane + 64];
    float2 p3 = g_partial[batch][lane + 96];
    float st  = (p0.x + p1.x) + (p2.x + p3.x);
    float st2 = (p0.y + p1.y) + (p2.y + p3.y);
    #pragma unroll
    for (int off = 16; off; off >>= 1) {
        st  += __shfl_xor_sync(0xFFFFFFFFu, st,  off);
        st2 += __shfl_xor_sync(0xFFFFFFFFu, st2, off);
    }
    if (lane == 0) {
        double c = -2.0 * (double)st / ((double)ELEM_PER_BATCH - (double)st2);
        if (c >  20.0) c =  20.0;
        if (c < -20.0) c = -20.0;
        g_k[batch] = (float)exp(-c);
        if (c_out) c_out[batch] = (float)c;
    }
}

// ---------------------------------------------------------------------------
// Pass 2: out = sigmoid(x+c) = (1+t) / ((1+k) + (1-k) t)  [exact identity],
// reading only the 64 MB fp16 T (target: L2 hits), writing 128 MB O.
// T reads are last-use (.cs) so consumed lines evict first; O stores are
// evict-first so the write stream doesn't displace yet-unread T.
// ---------------------------------------------------------------------------
__global__ void __launch_bounds__(O_THREADS)
out_kernel(float4* __restrict__ O)
{
    const size_t ubase = (size_t)blockIdx.x * O_U4_PER_BLOCK;
    const int batch = (int)(ubase >> 17);            // 2^17 uint4 per batch

    __shared__ float sk;
    if (threadIdx.x == 0) sk = __ldcg(&g_k[batch]);
    __syncthreads();
    const float k = sk;
    const float A = 1.0f + k;                        // denominator constant
    const float B = 1.0f - k;                        // denominator slope

    const uint4* __restrict__ T4 = reinterpret_cast<const uint4*>(g_t);

    #pragma unroll
    for (int it = 0; it < O_ITERS; it++) {
        const size_t u = ubase + (size_t)(it * O_THREADS + threadIdx.x);
        uint4 tv = __ldcs(&T4[u]);                   // last use -> evict-first
        unsigned w[4] = {tv.x, tv.y, tv.z, tv.w};
        float o[8];
        #pragma unroll
        for (int j = 0; j < 4; j++) {
            __half2 h = reinterpret_cast<const __half2&>(w[j]);
            float2 f = __half22float2(h);
            o[2*j]     = (1.0f + f.x) * rcp_fast(__fmaf_rn(B, f.x, A));
            o[2*j + 1] = (1.0f + f.y) * rcp_fast(__fmaf_rn(B, f.y, A));
        }
        float4 r0 = make_float4(o[0], o[1], o[2], o[3]);
        float4 r1 = make_float4(o[4], o[5], o[6], o[7]);
        __stcs(&O[2*u],     r0);                     // evict-first stores
        __stcs(&O[2*u + 1], r1);
    }
}

// ---------------------------------------------------------------------------
extern "C" void kernel_launch(void* const* d_in, const int* in_sizes, int n_in,
                              void* d_out, int out_size)
{
    const float* X = (const float*)d_in[0];
    float* out = (float*)d_out;

    const long long map_elems = (long long)NBATCH * ELEM_PER_BATCH;
    float* c_out = ((long long)out_size > map_elems) ? (out + map_elems) : nullptr;

    stats_kernel<<<S_BLOCKS, S_THREADS>>>((const float4*)X);
    solve_kernel<<<1, NBATCH * 32>>>(c_out);
    out_kernel<<<O_BLOCKS, O_THREADS>>>((float4*)out);
}